// round 15
// baseline (speedup 1.0000x reference)
#include <cuda_runtime.h>
#include <cuda_fp16.h>
#include <cstdint>

// ---------------- problem dims ----------------
#define B_DIM 8
#define C_DIM 256
#define N_TOK 1024
#define M_PIX 9216
#define L_DIM 2048
#define TEXT_B_STRIDE  262144    // 1024*256
#define IMG_B_STRIDE   2359296   // 256*9216

#define NITER 50
#define CONV_TOL_SQ 1e-4f
#define DENOM_SHIFT 100.0f

// E = exp(-0.1*cost) stored as fp16 scaled by 2^10 (E*1024 ~ 1.7 here)
#define ESCALE      1024.0f
#define ESCALE_INV  0.0009765625f       // 2^-10

// exp(-10*c) underflows fp32 normals for c > 8.73; contributions below are
// denormal-level (<6.8e-39) and vanish exactly against the +100 shift.
#define KEXP_CUT 8.8f
// E*2^10 threshold equivalent to cost <= 8.8 (exp(-0.88)*1024 = 424.7, conservative)
#define E_ACT 424.0f
#define NCB 144                          // M_PIX / 64 column blocks

// ---------------- device scratch (statics; no mallocs) ----------------
__device__ float g_sqA[N_TOK];
__device__ float g_sqB[M_PIX];
__device__ float g_u[N_TOK];
__device__ float g_v[M_PIX];
__device__ float g_normU[64];
__device__ float g_normV[64];
__device__ unsigned g_bar_count;
__device__ unsigned g_bar_gen;

// per-(row, 64-col-block) min of cost (exact fp32), from GEMM1 epilogue
__device__ float g_minc[(size_t)N_TOK * NCB];
__device__ int g_rowAny[N_TOK];
__device__ int g_colAny[NCB];

// fp16 operand buffers (K-major)
__device__ __half g_hA1[(size_t)N_TOK * L_DIM];  // text  [n][l]
__device__ __half g_hB1[(size_t)M_PIX * L_DIM];  // image [m][l]; reused as fp32
                                                 // split-K scratch after GEMM1
__device__ __half g_hT2[(size_t)N_TOK * M_PIX];  // E*2^10 [n][m]; becomes T2=E*v*2^10 in k_prep
__device__ __half g_hB2[(size_t)L_DIM * M_PIX];  // image [l][m]
__device__ __half g_hA3[(size_t)L_DIM * N_TOK];  // text  [l][n]
__device__ __half g_hT3[(size_t)M_PIX * N_TOK];  // T3=E*u*2^10 [m][n]

// ---------------- helpers ----------------
__device__ __forceinline__ uint32_t smem_to_u32(const void* p) {
    uint32_t a;
    asm("{ .reg .u64 t; cvta.to.shared.u64 t, %1; cvt.u32.u64 %0, t; }" : "=r"(a) : "l"(p));
    return a;
}
__device__ __forceinline__ void ldsm_x4(uint32_t* r, uint32_t a) {
    asm volatile("ldmatrix.sync.aligned.m8n8.x4.shared.b16 {%0,%1,%2,%3}, [%4];"
                 : "=r"(r[0]), "=r"(r[1]), "=r"(r[2]), "=r"(r[3]) : "r"(a));
}
__device__ __forceinline__ void mma_f16(float* c, const uint32_t* a, const uint32_t* b) {
    asm volatile(
        "mma.sync.aligned.m16n8k16.row.col.f32.f16.f16.f32 "
        "{%0,%1,%2,%3}, {%4,%5,%6,%7}, {%8,%9}, {%0,%1,%2,%3};"
        : "+f"(c[0]), "+f"(c[1]), "+f"(c[2]), "+f"(c[3])
        : "r"(a[0]), "r"(a[1]), "r"(a[2]), "r"(a[3]), "r"(b[0]), "r"(b[1]));
}
__device__ __forceinline__ void cp16(uint32_t dst, const void* src) {
    asm volatile("cp.async.cg.shared.global [%0], [%1], 16;" :: "r"(dst), "l"(src));
}
__device__ __forceinline__ void cp_commit() {
    asm volatile("cp.async.commit_group;" ::: "memory");
}
template <int N>
__device__ __forceinline__ void cp_wait() {
    asm volatile("cp.async.wait_group %0;" :: "n"(N) : "memory");
}
__device__ __forceinline__ uint32_t pack2h(float a, float b) {
    __half2 h = __floats2half2_rn(a, b);
    return *(uint32_t*)&h;
}
// generic slow-path K from stored E: K = exp(-10*cost) = (E*2^-10)^100
__device__ __forceinline__ float K_from_E(float e1024) {
    return __expf(100.0f * __logf(e1024 * ESCALE_INV));
}

// ---------------- init ----------------
__global__ void k_init() {
    int tid = blockIdx.x * blockDim.x + threadIdx.x;
    if (tid < N_TOK) { g_u[tid] = 1.0f; g_sqA[tid] = 0.0f; }
    if (tid < M_PIX) { g_v[tid] = 1.0f; g_sqB[tid] = 0.0f; }
    if (tid < 64) { g_normU[tid] = 0.0f; g_normV[tid] = 0.0f; }
    if (tid == 0) { g_bar_count = 0u; g_bar_gen = 0u; }
}

// ---------------- vectorized pack kernels ----------------
// pack text + fused sqA accumulation
__global__ void k_pack_text(const float* __restrict__ text) {
    __shared__ float t[32][33];
    const int b = blockIdx.z, n0 = blockIdx.y * 32, c0 = blockIdx.x * 32;
    const int tid = threadIdx.x, r = tid >> 3, c4 = (tid & 7) << 2;
    float4 v = *(const float4*)(text + (size_t)b * TEXT_B_STRIDE +
                                (size_t)(n0 + r) * C_DIM + c0 + c4);
    t[r][c4] = v.x; t[r][c4 + 1] = v.y; t[r][c4 + 2] = v.z; t[r][c4 + 3] = v.w;
    uint2 s1; s1.x = pack2h(v.x, v.y); s1.y = pack2h(v.z, v.w);
    *(uint2*)(g_hA1 + (size_t)(n0 + r) * L_DIM + b * C_DIM + c0 + c4) = s1;
    // sqA partial for row n0+r: sum over this tile's 32 c's
    float s = v.x * v.x + v.y * v.y + v.z * v.z + v.w * v.w;
    s += __shfl_down_sync(0xffffffffu, s, 4, 8);
    s += __shfl_down_sync(0xffffffffu, s, 2, 8);
    s += __shfl_down_sync(0xffffffffu, s, 1, 8);
    if ((tid & 7) == 0) atomicAdd(&g_sqA[n0 + r], s);
    __syncthreads();
    uint2 s2;
    s2.x = pack2h(t[c4][r], t[c4 + 1][r]);
    s2.y = pack2h(t[c4 + 2][r], t[c4 + 3][r]);
    *(uint2*)(g_hA3 + (size_t)(b * C_DIM + c0 + r) * N_TOK + n0 + c4) = s2;
}

// pack image + fused per-column sqB accumulation
__global__ void k_pack_image(const float* __restrict__ image) {
    __shared__ float t[32][33];
    __shared__ float ss[8][33];
    const int l0 = blockIdx.y * 32, m0 = blockIdx.x * 32;
    const int tid = threadIdx.x, r = tid >> 3, c4 = (tid & 7) << 2;
    float4 v = *(const float4*)(image + (size_t)(l0 + r) * M_PIX + m0 + c4);
    t[r][c4] = v.x; t[r][c4 + 1] = v.y; t[r][c4 + 2] = v.z; t[r][c4 + 3] = v.w;
    uint2 s1; s1.x = pack2h(v.x, v.y); s1.y = pack2h(v.z, v.w);
    *(uint2*)(g_hB2 + (size_t)(l0 + r) * M_PIX + m0 + c4) = s1;
    __syncthreads();
    uint2 s2;
    s2.x = pack2h(t[c4][r], t[c4 + 1][r]);
    s2.y = pack2h(t[c4 + 2][r], t[c4 + 3][r]);
    *(uint2*)(g_hB1 + (size_t)(m0 + r) * L_DIM + l0 + c4) = s2;
    {
        const int c = tid & 31, part = tid >> 5;
        float s = 0.0f;
#pragma unroll
        for (int k = 0; k < 4; ++k) s += t[part * 4 + k][c] * t[part * 4 + k][c];
        ss[part][c] = s;
    }
    __syncthreads();
    if (tid < 32) {
        float s = 0.0f;
#pragma unroll
        for (int j = 0; j < 8; ++j) s += ss[j][tid];
        atomicAdd(&g_sqB[m0 + tid], s);
    }
}

// ---------------- GEMM geometry (all single-term fp16) ----------------
#define SPAD 40
#define TILE_BYTES (128 * SPAD * 2)
#define OFF_A 0
#define OFF_B (TILE_BYTES)
#define STAGE (2 * TILE_BYTES)
#define SMEM_GEMM (3 * STAGE)        // 61440 -> 2 CTAs/SM

// =====================================================================
// GEMM1: cost = sqrt(sqA+sqB-2*A.B) in registers only; writes
// E = fp16(exp(-0.1*cost)*2^10) into g_hT2 and the per-block min table.
// =====================================================================
__global__ void __launch_bounds__(256, 2) k_gemm1() {
    extern __shared__ char sm[];
    const int tid = threadIdx.x, wid = tid >> 5, lane = tid & 31;
    const int wy = wid >> 1, wx = wid & 1;
    const int row0 = blockIdx.y * 128, col0 = blockIdx.x * 128;
    const uint32_t smb = smem_to_u32(sm);

    float acc[2][8][4] = {};

    const int ld_r = tid >> 2, ld_c = (tid & 3) << 3;
    const int a_r = lane & 15, a_c = (lane >> 4) << 3;
    const int b_r = (lane & 7) + (((lane >> 4) & 1) << 3), b_c = ((lane >> 3) & 1) << 3;

    const int KCH = L_DIM >> 5;

    auto issue = [&](int kc) {
        if (kc < KCH) {
            const int k0 = kc << 5;
            const uint32_t sb = smb + (kc % 3) * STAGE;
#pragma unroll
            for (int i = 0; i < 2; ++i) {
                int r = ld_r + i * 64;
                uint32_t so = (uint32_t)(r * SPAD + ld_c) * 2;
                cp16(sb + OFF_A + so, g_hA1 + (size_t)(row0 + r) * L_DIM + k0 + ld_c);
                cp16(sb + OFF_B + so, g_hB1 + (size_t)(col0 + r) * L_DIM + k0 + ld_c);
            }
        }
        cp_commit();
    };

    issue(0); issue(1);
    for (int kc = 0; kc < KCH; ++kc) {
        cp_wait<1>();
        __syncthreads();
        issue(kc + 2);
        const uint32_t sb = smb + (kc % 3) * STAGE;
#pragma unroll
        for (int kk = 0; kk < 2; ++kk) {
            uint32_t ah[2][4], bh[4][4];
#pragma unroll
            for (int mt = 0; mt < 2; ++mt) {
                uint32_t off = (uint32_t)((wy * 32 + mt * 16 + a_r) * SPAD + kk * 16 + a_c) * 2;
                ldsm_x4(ah[mt], sb + OFF_A + off);
            }
#pragma unroll
            for (int p = 0; p < 4; ++p) {
                uint32_t off = (uint32_t)((wx * 64 + p * 16 + b_r) * SPAD + kk * 16 + b_c) * 2;
                ldsm_x4(bh[p], sb + OFF_B + off);
            }
#pragma unroll
            for (int mt = 0; mt < 2; ++mt)
#pragma unroll
                for (int nt = 0; nt < 8; ++nt) {
                    const uint32_t bb[2] = { bh[nt >> 1][(nt & 1) * 2],
                                             bh[nt >> 1][(nt & 1) * 2 + 1] };
                    mma_f16(acc[mt][nt], ah[mt], bb);
                }
        }
    }

    const int rbase = row0 + wy * 32 + (lane >> 2);
    const int cbase = col0 + wx * 64 + ((lane & 3) << 1);
    float rmin[4] = { 1e30f, 1e30f, 1e30f, 1e30f };
#pragma unroll
    for (int mt = 0; mt < 2; ++mt) {
        int rA = rbase + mt * 16, rB = rA + 8;
        float saA = g_sqA[rA], saB = g_sqA[rB];
#pragma unroll
        for (int nt = 0; nt < 8; ++nt) {
            int cc = cbase + nt * 8;
            float sb0 = g_sqB[cc], sb1 = g_sqB[cc + 1];
            float cA0 = sqrtf(fmaxf(saA + sb0 - 2.0f * acc[mt][nt][0], 1e-12f));
            float cA1 = sqrtf(fmaxf(saA + sb1 - 2.0f * acc[mt][nt][1], 1e-12f));
            float cB0 = sqrtf(fmaxf(saB + sb0 - 2.0f * acc[mt][nt][2], 1e-12f));
            float cB1 = sqrtf(fmaxf(saB + sb1 - 2.0f * acc[mt][nt][3], 1e-12f));
            rmin[mt * 2]     = fminf(rmin[mt * 2],     fminf(cA0, cA1));
            rmin[mt * 2 + 1] = fminf(rmin[mt * 2 + 1], fminf(cB0, cB1));
            uint32_t eA = pack2h(expf(-0.1f * cA0) * ESCALE, expf(-0.1f * cA1) * ESCALE);
            uint32_t eB = pack2h(expf(-0.1f * cB0) * ESCALE, expf(-0.1f * cB1) * ESCALE);
            *(uint32_t*)(g_hT2 + (size_t)rA * M_PIX + cc) = eA;
            *(uint32_t*)(g_hT2 + (size_t)rB * M_PIX + cc) = eB;
        }
    }
#pragma unroll
    for (int i = 0; i < 4; ++i) {
        rmin[i] = fminf(rmin[i], __shfl_xor_sync(0xffffffffu, rmin[i], 1));
        rmin[i] = fminf(rmin[i], __shfl_xor_sync(0xffffffffu, rmin[i], 2));
    }
    if ((lane & 3) == 0) {
        const int cb = (col0 + wx * 64) >> 6;
        g_minc[(size_t)(rbase)      * NCB + cb] = rmin[0];
        g_minc[(size_t)(rbase + 8)  * NCB + cb] = rmin[1];
        g_minc[(size_t)(rbase + 16) * NCB + cb] = rmin[2];
        g_minc[(size_t)(rbase + 24) * NCB + cb] = rmin[3];
    }
}

// ---------------- min-table scan ----------------
__global__ void k_minscan() {
    __shared__ float sh[256];
    const int bid = blockIdx.x, tid = threadIdx.x;
    if (bid < 4) {
        const int n = bid * 256 + tid;
        const float* p = g_minc + (size_t)n * NCB;
        float mn = 1e30f;
        for (int cb = 0; cb < NCB; ++cb) mn = fminf(mn, p[cb]);
        g_rowAny[n] = (mn <= KEXP_CUT) ? 1 : 0;
    } else {
        const int cb = bid - 4;
        float mn = 1e30f;
        for (int n = tid; n < N_TOK; n += 256)
            mn = fminf(mn, g_minc[(size_t)n * NCB + cb]);
        sh[tid] = mn; __syncthreads();
        for (int off = 128; off > 0; off >>= 1) {
            if (tid < off) sh[tid] = fminf(sh[tid], sh[tid + off]);
            __syncthreads();
        }
        if (tid == 0) g_colAny[cb] = (sh[0] <= KEXP_CUT) ? 1 : 0;
    }
}

// ---------------- prep: T2 = E*v (in place), T3 = transpose(E)*u ----------------
__global__ void k_prep() {
    __shared__ float t[32][33];
    const int n0 = blockIdx.y * 32, m0 = blockIdx.x * 32;
    const int tid = threadIdx.x, r = tid >> 3, c4 = (tid & 7) << 2;
    uint2 e2 = *(uint2*)(g_hT2 + (size_t)(n0 + r) * M_PIX + m0 + c4);
    __half2* hp = (__half2*)&e2;
    float2 f01 = __half22float2(hp[0]);
    float2 f23 = __half22float2(hp[1]);
    float4 v4 = *(const float4*)(g_v + m0 + c4);
    const float un = g_u[n0 + r];
    uint2 s1;
    s1.x = pack2h(f01.x * v4.x, f01.y * v4.y);
    s1.y = pack2h(f23.x * v4.z, f23.y * v4.w);
    *(uint2*)(g_hT2 + (size_t)(n0 + r) * M_PIX + m0 + c4) = s1;
    t[r][c4] = f01.x * un; t[r][c4 + 1] = f01.y * un;
    t[r][c4 + 2] = f23.x * un; t[r][c4 + 3] = f23.y * un;
    __syncthreads();
    uint2 s2;
    s2.x = pack2h(t[c4][r], t[c4 + 1][r]);
    s2.y = pack2h(t[c4 + 2][r], t[c4 + 3][r]);
    *(uint2*)(g_hT3 + (size_t)(m0 + r) * N_TOK + n0 + c4) = s2;
}

// =====================================================================
// GEMM2+3 fused, single-term fp16, split-K=2 on GEMM2.
// G2: out_text[n,l] = u[n]*2^-10 * sum_m T2[n,m]*B2[l,m]
// G3: out_img[l,m]  = v[m]*2^-10 * sum_n A3[l,n]*T3[m,n]
// =====================================================================
#define G2_BLOCKS 256
#define G2_KCH_HALF 144

__global__ void __launch_bounds__(256, 2) k_gemm23(float* __restrict__ out_text,
                                                   float* __restrict__ out_img) {
    extern __shared__ char sm[];
    const int bid = blockIdx.x;
    const bool isG2 = (bid < G2_BLOCKS);
    int bx, by, ks = 0;
    if (isG2) { int b2 = bid & 127; bx = b2 & 15; by = b2 >> 4; ks = bid >> 7; }
    else { int b = bid - G2_BLOCKS; bx = b % 72; by = b / 72; }

    const __half *A_, *B_;
    int Ktot; float* out;
    if (isG2) {
        A_ = g_hT2; B_ = g_hB2; Ktot = M_PIX;
        out = ks ? (float*)g_hB1 : out_text;
    } else { A_ = g_hA3; B_ = g_hT3; Ktot = N_TOK; out = out_img; }

    const int tid = threadIdx.x, wid = tid >> 5, lane = tid & 31;
    const int wy = wid >> 1, wx = wid & 1;
    const int row0 = by * 128, col0 = bx * 128;
    const uint32_t smb = smem_to_u32(sm);

    float acc[2][8][4] = {};

    const int ld_r = tid >> 2, ld_c = (tid & 3) << 3;
    const int a_r = lane & 15, a_c = (lane >> 4) << 3;
    const int b_r = (lane & 7) + (((lane >> 4) & 1) << 3), b_c = ((lane >> 3) & 1) << 3;

    const int kc_beg = isG2 ? ks * G2_KCH_HALF : 0;
    const int kc_end = isG2 ? kc_beg + G2_KCH_HALF : (Ktot >> 5);

    auto issue = [&](int kc) {
        if (kc < kc_end) {
            const int k0 = kc << 5;
            const uint32_t sb = smb + (kc % 3) * STAGE;
#pragma unroll
            for (int i = 0; i < 2; ++i) {
                int r = ld_r + i * 64;
                uint32_t so = (uint32_t)(r * SPAD + ld_c) * 2;
                cp16(sb + OFF_A + so, A_ + (size_t)(row0 + r) * Ktot + k0 + ld_c);
                cp16(sb + OFF_B + so, B_ + (size_t)(col0 + r) * Ktot + k0 + ld_c);
            }
        }
        cp_commit();
    };

    issue(kc_beg); issue(kc_beg + 1);
    for (int kc = kc_beg; kc < kc_end; ++kc) {
        cp_wait<1>();
        __syncthreads();
        issue(kc + 2);
        const uint32_t sb = smb + (kc % 3) * STAGE;
#pragma unroll
        for (int kk = 0; kk < 2; ++kk) {
            uint32_t ah[2][4], bh[4][4];
#pragma unroll
            for (int mt = 0; mt < 2; ++mt) {
                uint32_t off = (uint32_t)((wy * 32 + mt * 16 + a_r) * SPAD + kk * 16 + a_c) * 2;
                ldsm_x4(ah[mt], sb + OFF_A + off);
            }
#pragma unroll
            for (int p = 0; p < 4; ++p) {
                uint32_t off = (uint32_t)((wx * 64 + p * 16 + b_r) * SPAD + kk * 16 + b_c) * 2;
                ldsm_x4(bh[p], sb + OFF_B + off);
            }
#pragma unroll
            for (int mt = 0; mt < 2; ++mt)
#pragma unroll
                for (int nt = 0; nt < 8; ++nt) {
                    const uint32_t bb[2] = { bh[nt >> 1][(nt & 1) * 2],
                                             bh[nt >> 1][(nt & 1) * 2 + 1] };
                    mma_f16(acc[mt][nt], ah[mt], bb);
                }
        }
    }

    const int rbase = row0 + wy * 32 + (lane >> 2);
    const int cbase = col0 + wx * 64 + ((lane & 3) << 1);
#pragma unroll
    for (int mt = 0; mt < 2; ++mt) {
        int rA = rbase + mt * 16, rB = rA + 8;
        float fA = 1.0f, fB = 1.0f;
        if (isG2) {
            fA = g_u[rA] * ESCALE_INV;
            fB = g_u[rB] * ESCALE_INV;
        }
#pragma unroll
        for (int nt = 0; nt < 8; ++nt) {
            int cc = cbase + nt * 8;
            float d0, d1, d2, d3;
            if (isG2) {
                d0 = acc[mt][nt][0] * fA; d1 = acc[mt][nt][1] * fA;
                d2 = acc[mt][nt][2] * fB; d3 = acc[mt][nt][3] * fB;
                int b = cc >> 8, c = cc & 255;
                float* pA = out + (size_t)b * TEXT_B_STRIDE + (size_t)rA * C_DIM + c;
                float* pB = out + (size_t)b * TEXT_B_STRIDE + (size_t)rB * C_DIM + c;
                *(float2*)pA = make_float2(d0, d1);
                *(float2*)pB = make_float2(d2, d3);
            } else {
                float f0 = g_v[cc] * ESCALE_INV, f1 = g_v[cc + 1] * ESCALE_INV;
                d0 = acc[mt][nt][0] * f0; d1 = acc[mt][nt][1] * f1;
                d2 = acc[mt][nt][2] * f0; d3 = acc[mt][nt][3] * f1;
                *(float2*)(out + (size_t)rA * M_PIX + cc) = make_float2(d0, d1);
                *(float2*)(out + (size_t)rB * M_PIX + cc) = make_float2(d2, d3);
            }
        }
    }
}

// combine split-K halves: out_text += scratch (deterministic)
__global__ void k_combine(float* __restrict__ out_text) {
    const float* scr = (const float*)g_hB1;
    size_t i = ((size_t)blockIdx.x * 256 + threadIdx.x) * 4;
    float4 o = *(float4*)(out_text + i);
    float4 s = *(const float4*)(scr + i);
    o.x += s.x; o.y += s.y; o.z += s.z; o.w += s.w;
    *(float4*)(out_text + i) = o;
}

// ---------------- Sinkhorn (persistent; mask fast path; E-based slow path) ----------------
__device__ __forceinline__ void grid_barrier(unsigned e, int nctas) {
    __syncthreads();
    if (threadIdx.x == 0) {
        __threadfence();
        unsigned t = atomicAdd(&g_bar_count, 1u) + 1u;
        if (t == (unsigned)nctas * e) {
            atomicExch(&g_bar_gen, e);
        } else {
            while (*((volatile unsigned*)&g_bar_gen) < e) __nanosleep(64);
        }
        __threadfence();
    }
    __syncthreads();
}

__global__ void k_sinkhorn() {
    __shared__ float4 sred4[256];
    float* sred = (float*)sred4;
    const int cta = blockIdx.x;
    const int tid = threadIdx.x;
    const int NC = gridDim.x;
    unsigned epoch = 0;
    for (int it = 0; it < NITER; ++it) {
        // ---- U phase ----
        for (int n = cta; n < N_TOK; n += NC) {
            const int any = __ldcg(&g_rowAny[n]);
            if (any) {
                const __half* row = g_hT2 + (size_t)n * M_PIX;
                float s = 0.0f;
                for (int m = tid << 2; m < M_PIX; m += 1024) {
                    uint2 e2 = *(const uint2*)(row + m);
                    __half2* hp = (__half2*)&e2;
                    float2 f01 = __half22float2(hp[0]);
                    float2 f23 = __half22float2(hp[1]);
                    if (f01.x >= E_ACT || f01.y >= E_ACT ||
                        f23.x >= E_ACT || f23.y >= E_ACT) {
                        float4 v4 = __ldcg((const float4*)(g_v + m));
                        s += K_from_E(f01.x) * v4.x + K_from_E(f01.y) * v4.y
                           + K_from_E(f23.x) * v4.z + K_from_E(f23.y) * v4.w;
                    }
                }
                sred[tid] = s; __syncthreads();
                for (int off = 128; off > 0; off >>= 1) {
                    if (tid < off) sred[tid] += sred[tid + off];
                    __syncthreads();
                }
            }
            if (tid == 0) {
                float base = any ? sred[0] : 0.0f;
                float un = 1.0f / (base + DENOM_SHIFT);
                float d = un - __ldcg(&g_u[n]);
                atomicAdd(&g_normU[it], d * d);
                g_u[n] = un;
            }
            __syncthreads();
        }
        ++epoch; grid_barrier(epoch, NC);
        // ---- V phase ----
        for (int blk = cta; blk < NCB; blk += NC) {
            const int col0 = blk * 64;
            const int any = __ldcg(&g_colAny[blk]);
            if (any) {
                const int cg = (tid & 15) << 2;
                const int sl = tid >> 4;
                float4 t4 = make_float4(0.f, 0.f, 0.f, 0.f);
                for (int n = sl; n < N_TOK; n += 16) {
                    uint2 e2 = *(const uint2*)(g_hT2 + (size_t)n * M_PIX + col0 + cg);
                    __half2* hp = (__half2*)&e2;
                    float2 f01 = __half22float2(hp[0]);
                    float2 f23 = __half22float2(hp[1]);
                    if (f01.x >= E_ACT || f01.y >= E_ACT ||
                        f23.x >= E_ACT || f23.y >= E_ACT) {
                        float un = __ldcg(&g_u[n]);
                        t4.x += K_from_E(f01.x) * un;
                        t4.y += K_from_E(f01.y) * un;
                        t4.z += K_from_E(f23.x) * un;
                        t4.w += K_from_E(f23.y) * un;
                    }
                }
                sred4[tid] = t4; __syncthreads();
            }
            if (tid < 16) {
                float4 a = make_float4(0.f, 0.f, 0.f, 0.f);
                if (any) {
                    a = sred4[tid];
#pragma unroll
                    for (int j = 1; j < 16; ++j) {
                        float4 b = sred4[tid + j * 16];
                        a.x += b.x; a.y += b.y; a.z += b.z; a.w += b.w;
                    }
                }
                const int m = col0 + (tid << 2);
                float vs[4] = { a.x, a.y, a.z, a.w };
                float nacc = 0.0f;
#pragma unroll
                for (int j = 0; j < 4; ++j) {
                    float vn = 1.0f / (vs[j] + DENOM_SHIFT);
                    float d = vn - __ldcg(&g_v[m + j]);
                    nacc += d * d;
                    g_v[m + j] = vn;
                }
                atomicAdd(&g_normV[it], nacc);
            }
            __syncthreads();
        }
        ++epoch; grid_barrier(epoch, NC);
        float nu = __ldcg(&g_normU[it]);
        float nv = __ldcg(&g_normV[it]);
        if (nu < CONV_TOL_SQ && nv < CONV_TOL_SQ) break;
    }
}

// ---------------- launch ----------------
extern "C" void kernel_launch(void* const* d_in, const int* in_sizes, int n_in,
                              void* d_out, int out_size) {
    const float* text  = (const float*)d_in[0];
    const float* image = (const float*)d_in[1];
    float* out_text = (float*)d_out;
    float* out_img  = out_text + (size_t)B_DIM * N_TOK * C_DIM;

    cudaFuncSetAttribute(k_gemm1, cudaFuncAttributeMaxDynamicSharedMemorySize, SMEM_GEMM);
    cudaFuncSetAttribute(k_gemm23, cudaFuncAttributeMaxDynamicSharedMemorySize, SMEM_GEMM);

    k_init<<<36, 256>>>();
    k_pack_text<<<dim3(C_DIM / 32, N_TOK / 32, B_DIM), 256>>>(text);
    k_pack_image<<<dim3(M_PIX / 32, L_DIM / 32), 256>>>(image);

    // GEMM1: writes E (fp16) + exact min table; no fp32 cost matrix
    k_gemm1<<<dim3(M_PIX / 128, N_TOK / 128), 256, SMEM_GEMM>>>();
    k_minscan<<<4 + NCB, 256>>>();

    k_sinkhorn<<<148, 256>>>();
    k_prep<<<dim3(M_PIX / 32, N_TOK / 32), 256>>>();

    // GEMM2 (split-K=2, 256 CTAs) + GEMM3 (1152 CTAs) fused
    k_gemm23<<<G2_BLOCKS + 1152, 256, SMEM_GEMM>>>(out_text, out_img);
    k_combine<<<(B_DIM * N_TOK * C_DIM) / (256 * 4), 256>>>(out_text);
}